// round 11
// baseline (speedup 1.0000x reference)
#include <cuda_runtime.h>
#include <cuda_bf16.h>
#include <cstdint>
#include <math.h>

// ---------------------------------------------------------------------------
// Problem constants
// ---------------------------------------------------------------------------
#define N_NODES 100000
#define M_PAD   100096          // 782 * 128
#define BN_COLS 256

// ---------------------------------------------------------------------------
// Scratch (device globals; zero-initialized; no allocation allowed)
// A_i layouts (bf16): [hi region (Kpad)][lo region (Kpad)], ld = 2*Kpad
//   A0: Kpad=256  (agg 0..99,  self 100..199, pad->255)
//   A1: Kpad=448  (agg 0..199, self 200..399, pad->447)
//   A2: Kpad=256  (agg 0..127, self 128..255)
//   A3: Kpad=128
//   A4: Kpad=128
// Wt_i (bf16): rows = padded N, cols = 2*Kpad: [W_hi | W_lo], zeros in pads
// ---------------------------------------------------------------------------
__device__ __align__(1024) __nv_bfloat16 g_A0[(size_t)M_PAD * 512];
__device__ __align__(1024) __nv_bfloat16 g_A1[(size_t)M_PAD * 896];
__device__ __align__(1024) __nv_bfloat16 g_A2[(size_t)M_PAD * 512];
__device__ __align__(1024) __nv_bfloat16 g_A3[(size_t)M_PAD * 256];
__device__ __align__(1024) __nv_bfloat16 g_A4[(size_t)M_PAD * 256];
__device__ float  g_h0[(size_t)M_PAD * 200];
__device__ float  g_h1[(size_t)M_PAD * 128];
__device__ float  g_h4[(size_t)M_PAD * 256];
__device__ __align__(1024) __nv_bfloat16 g_Wt0[256 * 512];
__device__ __align__(1024) __nv_bfloat16 g_Wt1[128 * 896];
__device__ __align__(1024) __nv_bfloat16 g_Wt2[128 * 512];
__device__ __align__(1024) __nv_bfloat16 g_Wt3[128 * 256];
__device__ __align__(1024) __nv_bfloat16 g_Wt4[256 * 256];
__device__ float  g_bias[3 * 256];
__device__ int    g_row_ptr[N_NODES + 1];
__device__ double g_part[512 * 512];
__device__ float  g_scale[BN_COLS];
__device__ float  g_shift[BN_COLS];

// ---------------------------------------------------------------------------
// PTX helpers (baseline features only; nothing sm_103a-gated)
// ---------------------------------------------------------------------------
__device__ __forceinline__ void cpa16(uint32_t dst, const void* src) {
    asm volatile("cp.async.cg.shared.global [%0], [%1], 16;\n"
                 :: "r"(dst), "l"(src));
}
__device__ __forceinline__ void cpa_commit() {
    asm volatile("cp.async.commit_group;\n" ::: "memory");
}
__device__ __forceinline__ void cpa_wait1() {
    asm volatile("cp.async.wait_group 1;\n" ::: "memory");
}
__device__ __forceinline__ void cpa_wait0() {
    asm volatile("cp.async.wait_group 0;\n" ::: "memory");
}
__device__ __forceinline__ void ldm_x4(uint32_t addr, uint32_t& r0, uint32_t& r1,
                                       uint32_t& r2, uint32_t& r3) {
    asm volatile("ldmatrix.sync.aligned.m8n8.x4.shared.b16 {%0,%1,%2,%3}, [%4];"
                 : "=r"(r0), "=r"(r1), "=r"(r2), "=r"(r3) : "r"(addr));
}
__device__ __forceinline__ void mma_bf16(float& c0, float& c1, float& c2, float& c3,
                                         uint32_t a0, uint32_t a1, uint32_t a2,
                                         uint32_t a3, uint32_t b0, uint32_t b1) {
    asm volatile(
        "mma.sync.aligned.m16n8k16.row.col.f32.bf16.bf16.f32 "
        "{%0,%1,%2,%3}, {%4,%5,%6,%7}, {%8,%9}, {%0,%1,%2,%3};"
        : "+f"(c0), "+f"(c1), "+f"(c2), "+f"(c3)
        : "r"(a0), "r"(a1), "r"(a2), "r"(a3), "r"(b0), "r"(b1));
}
__device__ __forceinline__ void split_bf16(float v, __nv_bfloat16& hi,
                                           __nv_bfloat16& lo) {
    hi = __float2bfloat16(v);
    lo = __float2bfloat16(v - __bfloat162float(hi));
}

// ---------------------------------------------------------------------------
// CSR row_ptr from sorted edge_row
// ---------------------------------------------------------------------------
__global__ void build_row_ptr(const int* __restrict__ row, int E, int N,
                              int* __restrict__ rp) {
    int i = blockIdx.x * blockDim.x + threadIdx.x;
    if (i > N) return;
    int lo = 0, hi = E;
    while (lo < hi) {
        int mid = (lo + hi) >> 1;
        if (row[mid] < i) lo = mid + 1; else hi = mid;
    }
    rp[i] = lo;
}

// ---------------------------------------------------------------------------
// Prep: x -> A0 self region (hi/lo bf16)
// ---------------------------------------------------------------------------
__global__ void xprep_kernel(const float* __restrict__ x,
                             __nv_bfloat16* __restrict__ A0) {
    int idx = blockIdx.x * blockDim.x + threadIdx.x;
    if (idx >= N_NODES * 100) return;
    int m = idx / 100, c = idx % 100;
    __nv_bfloat16 hi, lo;
    split_bf16(__ldg(x + idx), hi, lo);
    A0[(size_t)m * 512 + 100 + c] = hi;
    A0[(size_t)m * 512 + 356 + c] = lo;   // 256 + 100
}

// ---------------------------------------------------------------------------
// Prep: W (K x Nlog row-major; dual = [Wa; Wb]) -> Wt (N x 2*Kpad bf16)
// ---------------------------------------------------------------------------
__global__ void build_wt_kernel(const float* __restrict__ Wa,
                                const float* __restrict__ Wb,
                                int F, int Keff, int Kpad, int Nlog,
                                __nv_bfloat16* __restrict__ dst) {
    int idx = blockIdx.x * blockDim.x + threadIdx.x;
    if (idx >= Nlog * Keff) return;
    int n = idx / Keff, k = idx % Keff;
    float w = (k < F) ? __ldg(Wa + (size_t)k * Nlog + n)
                      : __ldg(Wb + (size_t)(k - F) * Nlog + n);
    __nv_bfloat16 hi, lo;
    split_bf16(w, hi, lo);
    dst[(size_t)n * (2 * Kpad) + k] = hi;
    dst[(size_t)n * (2 * Kpad) + Kpad + k] = lo;
}

__global__ void prep_bias_kernel(const float* b0, const float* bs0,
                                 const float* b1, const float* bs1,
                                 const float* b2, const float* bs2,
                                 float* __restrict__ bias) {
    int t = threadIdx.x;
    bias[t]       = (t < 200) ? b0[t] + bs0[t] : 0.f;
    bias[256 + t] = (t < 128) ? b1[t] + bs1[t] : 0.f;
    bias[512 + t] = (t < 128) ? b2[t] + bs2[t] : 0.f;
}

// ---------------------------------------------------------------------------
// SpMM: warp per node, float4 features, 4-edge unroll (MLP=4), writes bf16
// hi/lo into the next GEMM's A buffer. Deterministic accumulation order:
// acc over i, i+1, i+2, i+3 sequentially within the unrolled body.
// ---------------------------------------------------------------------------
__global__ void __launch_bounds__(256) spmm_kernel(
    const float* __restrict__ src, int sstride,
    const int* __restrict__ col, const float* __restrict__ val,
    const int* __restrict__ rp,
    __nv_bfloat16* __restrict__ dstA, int ldA, int loOff, int F4) {
    int warp = (blockIdx.x * blockDim.x + threadIdx.x) >> 5;
    if (warp >= N_NODES) return;
    int lane = threadIdx.x & 31;
    int s = __ldg(rp + warp), e = __ldg(rp + warp + 1);
    __nv_bfloat16* arow = dstA + (size_t)warp * ldA;
    for (int f = lane; f < F4; f += 32) {
        float4 acc = make_float4(0.f, 0.f, 0.f, 0.f);
        int i = s;
        for (; i + 3 < e; i += 4) {
            int   c0 = __ldg(col + i),     c1 = __ldg(col + i + 1);
            int   c2 = __ldg(col + i + 2), c3 = __ldg(col + i + 3);
            float v0 = __ldg(val + i),     v1 = __ldg(val + i + 1);
            float v2 = __ldg(val + i + 2), v3 = __ldg(val + i + 3);
            float4 x0 = __ldg((const float4*)(src + (size_t)c0 * sstride) + f);
            float4 x1 = __ldg((const float4*)(src + (size_t)c1 * sstride) + f);
            float4 x2 = __ldg((const float4*)(src + (size_t)c2 * sstride) + f);
            float4 x3 = __ldg((const float4*)(src + (size_t)c3 * sstride) + f);
            acc.x = fmaf(v0, x0.x, acc.x); acc.y = fmaf(v0, x0.y, acc.y);
            acc.z = fmaf(v0, x0.z, acc.z); acc.w = fmaf(v0, x0.w, acc.w);
            acc.x = fmaf(v1, x1.x, acc.x); acc.y = fmaf(v1, x1.y, acc.y);
            acc.z = fmaf(v1, x1.z, acc.z); acc.w = fmaf(v1, x1.w, acc.w);
            acc.x = fmaf(v2, x2.x, acc.x); acc.y = fmaf(v2, x2.y, acc.y);
            acc.z = fmaf(v2, x2.z, acc.z); acc.w = fmaf(v2, x2.w, acc.w);
            acc.x = fmaf(v3, x3.x, acc.x); acc.y = fmaf(v3, x3.y, acc.y);
            acc.z = fmaf(v3, x3.z, acc.z); acc.w = fmaf(v3, x3.w, acc.w);
        }
        for (; i < e; ++i) {
            int   c0 = __ldg(col + i);
            float v0 = __ldg(val + i);
            float4 x0 = __ldg((const float4*)(src + (size_t)c0 * sstride) + f);
            acc.x = fmaf(v0, x0.x, acc.x); acc.y = fmaf(v0, x0.y, acc.y);
            acc.z = fmaf(v0, x0.z, acc.z); acc.w = fmaf(v0, x0.w, acc.w);
        }
        __nv_bfloat16 h0, l0, h1, l1, h2, l2, h3, l3;
        split_bf16(acc.x, h0, l0); split_bf16(acc.y, h1, l1);
        split_bf16(acc.z, h2, l2); split_bf16(acc.w, h3, l3);
        __nv_bfloat162* ph = (__nv_bfloat162*)(arow + f * 4);
        __nv_bfloat162* pl = (__nv_bfloat162*)(arow + loOff + f * 4);
        ph[0] = __nv_bfloat162(h0, h1); ph[1] = __nv_bfloat162(h2, h3);
        pl[0] = __nv_bfloat162(l0, l1); pl[1] = __nv_bfloat162(l2, l3);
    }
}

// ---------------------------------------------------------------------------
// bf16-split GEMM via mma.sync (HMMA path, baseline PTX).
// C(128 x 64 per CTA) = A @ Wt^T with 3-phase split:
//   (Ahi,Whi), (Alo,Whi), (Ahi,Wlo)   [phases = K regions, same accumulator]
// A: row-major, ld = 2*Kpad bf16. Wt: Nrows x 2*Kpad bf16 (B col-major view).
// K chunks of 64; 2-stage cp.async pipeline; padded smem stride 72 bf16.
// 8 warps: 4(M) x 2(N); warp tile 32x32 = 2 m16 x 4 n8 fragments.
// Epilogue: bias + relu; writes fp32 C (optional) and bf16 hi/lo next-A.
// ---------------------------------------------------------------------------
__global__ void __launch_bounds__(256) gemm_mma_kernel(
    const __nv_bfloat16* __restrict__ A, int Kpad,
    const __nv_bfloat16* __restrict__ Wt,
    const float* __restrict__ bias, int Nlog,
    float* __restrict__ Cf, int ldc,
    __nv_bfloat16* __restrict__ nxt, int ldn, int hiOff, int loOff,
    int relu, int M) {
    extern __shared__ __align__(16) char smem[];
    const int tid  = threadIdx.x;
    const int l    = tid & 31;
    const int wid  = tid >> 5;
    const int wm   = wid >> 1;        // 0..3
    const int wn   = wid & 1;         // 0..1
    const int row0 = blockIdx.y * 128;
    const int col0 = blockIdx.x * 64;
    const int ldA  = 2 * Kpad;
    const int R    = Kpad >> 6;
    const int C    = 3 * R;

    const uint32_t sbase = (uint32_t)__cvta_generic_to_shared(smem);
    const uint32_t aSt   = 128 * 72 * 2;   // 18432 B per A stage
    const uint32_t bSt   = 64 * 72 * 2;    //  9216 B per B stage
    const uint32_t stage = aSt + bSt;      // 27648

    float acc[2][4][4];
#pragma unroll
    for (int i = 0; i < 2; ++i)
#pragma unroll
        for (int j = 0; j < 4; ++j)
#pragma unroll
            for (int k = 0; k < 4; ++k) acc[i][j][k] = 0.f;

    auto load_chunk = [&](int c) {
        const int s = c & 1;
        const uint32_t aB = sbase + (uint32_t)s * stage;
        const uint32_t bB = aB + aSt;
        const int reg = c / R, wi = c - reg * R;
        const int aCol = (reg == 1 ? Kpad : 0) + wi * 64;
        const int wCol = (reg == 2 ? Kpad : 0) + wi * 64;
        const __nv_bfloat16* aSrc = A + (size_t)row0 * ldA + aCol;
#pragma unroll
        for (int it = 0; it < 4; ++it) {
            int idx = tid + it * 256;
            int r = idx >> 3, g = idx & 7;
            cpa16(aB + (uint32_t)(r * 72 + g * 8) * 2,
                  aSrc + (size_t)r * ldA + g * 8);
        }
        const __nv_bfloat16* wSrc = Wt + (size_t)col0 * ldA + wCol;
#pragma unroll
        for (int it = 0; it < 2; ++it) {
            int idx = tid + it * 256;
            int r = idx >> 3, g = idx & 7;
            cpa16(bB + (uint32_t)(r * 72 + g * 8) * 2,
                  wSrc + (size_t)r * ldA + g * 8);
        }
        cpa_commit();
    };

    load_chunk(0);
    if (C > 1) load_chunk(1);

    // ldmatrix per-lane base offsets (bytes)
    const uint32_t aLdm = (uint32_t)(((l & 15) * 72 + (l >> 4) * 8) * 2
                                     + (wm * 32) * 144);
    const uint32_t bLdm = (uint32_t)((((l & 7) + ((l >> 4) << 3)) * 72
                                     + ((l >> 3) & 1) * 8) * 2
                                     + (wn * 32) * 144);

    for (int c = 0; c < C; ++c) {
        if (c + 1 < C) cpa_wait1(); else cpa_wait0();
        __syncthreads();
        const int s = c & 1;
        const uint32_t aB = sbase + (uint32_t)s * stage;
        const uint32_t bB = aB + aSt;
#pragma unroll
        for (int ks = 0; ks < 4; ++ks) {
            uint32_t af[2][4], bf[2][4];
#pragma unroll
            for (int mt = 0; mt < 2; ++mt)
                ldm_x4(aB + aLdm + (uint32_t)(ks * 32 + mt * 16 * 144),
                       af[mt][0], af[mt][1], af[mt][2], af[mt][3]);
#pragma unroll
            for (int np = 0; np < 2; ++np)
                ldm_x4(bB + bLdm + (uint32_t)(ks * 32 + np * 16 * 144),
                       bf[np][0], bf[np][1], bf[np][2], bf[np][3]);
#pragma unroll
            for (int mt = 0; mt < 2; ++mt)
#pragma unroll
                for (int nt = 0; nt < 4; ++nt)
                    mma_bf16(acc[mt][nt][0], acc[mt][nt][1],
                             acc[mt][nt][2], acc[mt][nt][3],
                             af[mt][0], af[mt][1], af[mt][2], af[mt][3],
                             bf[nt >> 1][(nt & 1) * 2],
                             bf[nt >> 1][(nt & 1) * 2 + 1]);
        }
        __syncthreads();
        if (c + 2 < C) load_chunk(c + 2);
    }

    // ---- epilogue ----
    const int mrow = l >> 2;          // 0..7
    const int ncol = (l & 3) * 2;
#pragma unroll
    for (int mt = 0; mt < 2; ++mt) {
        const int rbase = row0 + wm * 32 + mt * 16 + mrow;
#pragma unroll
        for (int h = 0; h < 2; ++h) {
            const int row = rbase + h * 8;
            if (row >= M) continue;
            float* crow = Cf ? Cf + (size_t)row * ldc : (float*)0;
            __nv_bfloat16* nrow = nxt ? nxt + (size_t)row * ldn
                                      : (__nv_bfloat16*)0;
#pragma unroll
            for (int nt = 0; nt < 4; ++nt) {
                const int cg = col0 + wn * 32 + nt * 8 + ncol;
                if (cg >= Nlog) continue;
                float v0 = acc[mt][nt][h * 2 + 0] + __ldg(bias + cg);
                float v1 = acc[mt][nt][h * 2 + 1] + __ldg(bias + cg + 1);
                if (relu) { v0 = fmaxf(v0, 0.f); v1 = fmaxf(v1, 0.f); }
                if (crow) {
                    float2 fv; fv.x = v0; fv.y = v1;
                    *(float2*)(crow + cg) = fv;
                }
                if (nrow) {
                    __nv_bfloat16 h0, l0, h1, l1;
                    split_bf16(v0, h0, l0);
                    split_bf16(v1, h1, l1);
                    *(__nv_bfloat162*)(nrow + hiOff + cg) = __nv_bfloat162(h0, h1);
                    *(__nv_bfloat162*)(nrow + loOff + cg) = __nv_bfloat162(l0, l1);
                }
            }
        }
    }
}

// ---------------------------------------------------------------------------
// fc2b (fused BN apply + relu): out = relu(h4*scale+shift) @ W + b
// ---------------------------------------------------------------------------
__global__ void __launch_bounds__(256) fc2b_kernel(
    const float* __restrict__ A, const float* __restrict__ W,
    const float* __restrict__ bias,
    const float* __restrict__ scale, const float* __restrict__ shift,
    float* __restrict__ out, int M) {
    __shared__ float Ws[256][20];
    __shared__ float sS[256], sB[256];
    for (int i = threadIdx.x; i < 256 * 18; i += 256)
        Ws[i / 18][i % 18] = __ldg(W + i);
    Ws[threadIdx.x][18] = 0.f;
    Ws[threadIdx.x][19] = 0.f;
    sS[threadIdx.x] = __ldg(scale + threadIdx.x);
    sB[threadIdx.x] = __ldg(shift + threadIdx.x);
    __syncthreads();

    int row = blockIdx.x * 256 + threadIdx.x;
    if (row >= M) return;
    const float4* a = (const float4*)(A + (size_t)row * 256);

    float acc[18];
#pragma unroll
    for (int j = 0; j < 18; ++j) acc[j] = 0.f;

    for (int k4 = 0; k4 < 64; ++k4) {
        float4 av = __ldg(a + k4);
        const int kb = k4 * 4;
        float avs[4];
        avs[0] = fmaxf(fmaf(av.x, sS[kb + 0], sB[kb + 0]), 0.f);
        avs[1] = fmaxf(fmaf(av.y, sS[kb + 1], sB[kb + 1]), 0.f);
        avs[2] = fmaxf(fmaf(av.z, sS[kb + 2], sB[kb + 2]), 0.f);
        avs[3] = fmaxf(fmaf(av.w, sS[kb + 3], sB[kb + 3]), 0.f);
#pragma unroll
        for (int u = 0; u < 4; ++u) {
            int k = kb + u;
            float va = avs[u];
            const float* wr = &Ws[k][0];
            float4 w0 = *(const float4*)(wr + 0);
            float4 w1 = *(const float4*)(wr + 4);
            float4 w2 = *(const float4*)(wr + 8);
            float4 w3 = *(const float4*)(wr + 12);
            float2 w4 = *(const float2*)(wr + 16);
            acc[0]  = fmaf(va, w0.x, acc[0]);  acc[1]  = fmaf(va, w0.y, acc[1]);
            acc[2]  = fmaf(va, w0.z, acc[2]);  acc[3]  = fmaf(va, w0.w, acc[3]);
            acc[4]  = fmaf(va, w1.x, acc[4]);  acc[5]  = fmaf(va, w1.y, acc[5]);
            acc[6]  = fmaf(va, w1.z, acc[6]);  acc[7]  = fmaf(va, w1.w, acc[7]);
            acc[8]  = fmaf(va, w2.x, acc[8]);  acc[9]  = fmaf(va, w2.y, acc[9]);
            acc[10] = fmaf(va, w2.z, acc[10]); acc[11] = fmaf(va, w2.w, acc[11]);
            acc[12] = fmaf(va, w3.x, acc[12]); acc[13] = fmaf(va, w3.y, acc[13]);
            acc[14] = fmaf(va, w3.z, acc[14]); acc[15] = fmaf(va, w3.w, acc[15]);
            acc[16] = fmaf(va, w4.x, acc[16]); acc[17] = fmaf(va, w4.y, acc[17]);
        }
    }
    float* orow = out + (size_t)row * 18;
#pragma unroll
    for (int j = 0; j < 18; ++j) orow[j] = acc[j] + __ldg(bias + j);
}

// ---------------------------------------------------------------------------
// Batchnorm: deterministic two-stage reduction in fp64
// ---------------------------------------------------------------------------
__global__ void __launch_bounds__(BN_COLS) bn_partial(
    const float* __restrict__ h, int M, double* __restrict__ part) {
    int c = threadIdx.x;
    double s = 0.0, q = 0.0;
    for (int r = blockIdx.x; r < M; r += gridDim.x) {
        double v = (double)h[(size_t)r * BN_COLS + c];
        s += v;
        q += v * v;
    }
    part[blockIdx.x * 512 + c]       = s;
    part[blockIdx.x * 512 + 256 + c] = q;
}

__global__ void __launch_bounds__(BN_COLS) bn_finalize(
    const double* __restrict__ part, int G, int M,
    const float* __restrict__ gamma, const float* __restrict__ beta,
    float* __restrict__ scale, float* __restrict__ shift) {
    int c = threadIdx.x;
    double s = 0.0, q = 0.0;
    for (int i = 0; i < G; ++i) {
        s += part[i * 512 + c];
        q += part[i * 512 + 256 + c];
    }
    double mean = s / M;
    double var  = q / M - mean * mean;
    float sc = gamma[c] * rsqrtf((float)var + 1e-5f);
    scale[c] = sc;
    shift[c] = beta[c] - (float)mean * sc;
}

// ---------------------------------------------------------------------------
// Launcher
// NOTE: launch order is arranged so ncu's "-s 5 -c 1" capture (6th launch)
// lands on the layer-0 spmm_kernel, not a trivial prep kernel.
// ---------------------------------------------------------------------------
extern "C" void kernel_launch(void* const* d_in, const int* in_sizes, int n_in,
                              void* d_out, int out_size) {
    const float* x        = (const float*)d_in[0];
    const int*   edge_row = (const int*)  d_in[1];
    const int*   edge_col = (const int*)  d_in[2];
    const float* edge_val = (const float*)d_in[3];
    const float* gc0_W  = (const float*)d_in[4];
    const float* gc0_b  = (const float*)d_in[5];
    const float* gc0_Ws = (const float*)d_in[6];
    const float* gc0_bs = (const float*)d_in[7];
    const float* gc1_W  = (const float*)d_in[8];
    const float* gc1_b  = (const float*)d_in[9];
    const float* gc1_Ws = (const float*)d_in[10];
    const float* gc1_bs = (const float*)d_in[11];
    const float* gc2_W  = (const float*)d_in[12];
    const float* gc2_b  = (const float*)d_in[13];
    const float* gc2_Ws = (const float*)d_in[14];
    const float* gc2_bs = (const float*)d_in[15];
    const float* fc1_W  = (const float*)d_in[16];
    const float* fc1_b  = (const float*)d_in[17];
    const float* fc2a_W = (const float*)d_in[18];
    const float* fc2a_b = (const float*)d_in[19];
    const float* bn_g   = (const float*)d_in[20];
    const float* bn_b   = (const float*)d_in[21];
    const float* fc2b_W = (const float*)d_in[22];
    const float* fc2b_b = (const float*)d_in[23];
    float* out = (float*)d_out;

    const int M = N_NODES;
    const int E = in_sizes[1];

    __nv_bfloat16 *A0, *A1, *A2, *A3, *A4, *Wt0, *Wt1, *Wt2, *Wt3, *Wt4;
    float *h0, *h1, *h4, *bias, *scale, *shift;
    int* rp;
    double* part;
    cudaGetSymbolAddress((void**)&A0,  g_A0);
    cudaGetSymbolAddress((void**)&A1,  g_A1);
    cudaGetSymbolAddress((void**)&A2,  g_A2);
    cudaGetSymbolAddress((void**)&A3,  g_A3);
    cudaGetSymbolAddress((void**)&A4,  g_A4);
    cudaGetSymbolAddress((void**)&Wt0, g_Wt0);
    cudaGetSymbolAddress((void**)&Wt1, g_Wt1);
    cudaGetSymbolAddress((void**)&Wt2, g_Wt2);
    cudaGetSymbolAddress((void**)&Wt3, g_Wt3);
    cudaGetSymbolAddress((void**)&Wt4, g_Wt4);
    cudaGetSymbolAddress((void**)&h0,  g_h0);
    cudaGetSymbolAddress((void**)&h1,  g_h1);
    cudaGetSymbolAddress((void**)&h4,  g_h4);
    cudaGetSymbolAddress((void**)&bias, g_bias);
    cudaGetSymbolAddress((void**)&rp,   g_row_ptr);
    cudaGetSymbolAddress((void**)&part, g_part);
    cudaGetSymbolAddress((void**)&scale, g_scale);
    cudaGetSymbolAddress((void**)&shift, g_shift);

    // dynamic smem: 2 stages * (18432 + 9216) = 55296 B
    const int SMEM = 55296;
    cudaFuncSetAttribute(gemm_mma_kernel,
                         cudaFuncAttributeMaxDynamicSharedMemorySize, SMEM);

    const int spmm_grid = (M + 7) / 8;    // 8 warps / 256-thread block
    const int GY = 782;                   // M tiles of 128

    // ---- prep part 1 (launches 1-5) ----
    build_row_ptr<<<(M + 256) / 256, 256>>>(edge_row, E, M, rp);               // 1
    prep_bias_kernel<<<1, 256>>>(gc0_b, gc0_bs, gc1_b, gc1_bs, gc2_b, gc2_bs,
                                 bias);                                        // 2
    build_wt_kernel<<<(200 * 200 + 255) / 256, 256>>>(gc0_W, gc0_Ws, 100, 200, 256, 200, Wt0);  // 3
    build_wt_kernel<<<(128 * 400 + 255) / 256, 256>>>(gc1_W, gc1_Ws, 200, 400, 448, 128, Wt1);  // 4
    build_wt_kernel<<<(128 * 256 + 255) / 256, 256>>>(gc2_W, gc2_Ws, 128, 256, 256, 128, Wt2);  // 5

    // ---- layer 0 spmm: launch #6 (ncu -s 5 -c 1 captures this) ----
    spmm_kernel<<<spmm_grid, 256>>>(x, 100, edge_col, edge_val, rp,
                                    A0, 512, 256, 25);                         // 6

    // ---- prep part 2 (independent of spmm/gemm layer 0 inputs they follow) --
    xprep_kernel<<<(M * 100 + 255) / 256, 256>>>(x, A0);                       // 7
    build_wt_kernel<<<(128 * 128 + 255) / 256, 256>>>(fc1_W, fc1_W, 128, 128, 128, 128, Wt3);   // 8
    build_wt_kernel<<<(256 * 128 + 255) / 256, 256>>>(fc2a_W, fc2a_W, 128, 128, 128, 256, Wt4); // 9

    // ---- layer 0 gemm: h0 = relu([agg|x]@W0+b); also fills A1 self ----
    gemm_mma_kernel<<<dim3(4, GY), 256, SMEM>>>(A0, 256, Wt0, bias, 200,
                                                h0, 200, A1, 896, 200, 648, 1, M);
    // ---- layer 1 ----
    spmm_kernel<<<spmm_grid, 256>>>(h0, 200, edge_col, edge_val, rp,
                                    A1, 896, 448, 50);
    gemm_mma_kernel<<<dim3(2, GY), 256, SMEM>>>(A1, 448, Wt1, bias + 256, 128,
                                                h1, 128, A2, 512, 128, 384, 1, M);
    // ---- layer 2 ----
    spmm_kernel<<<spmm_grid, 256>>>(h1, 128, edge_col, edge_val, rp,
                                    A2, 512, 256, 32);
    gemm_mma_kernel<<<dim3(2, GY), 256, SMEM>>>(A2, 256, Wt2, bias + 512, 128,
                                                (float*)0, 0, A3, 256, 0, 128, 1, M);
    // ---- fc1 ----
    gemm_mma_kernel<<<dim3(2, GY), 256, SMEM>>>(A3, 128, Wt3, fc1_b, 128,
                                                (float*)0, 0, A4, 256, 0, 128, 1, M);
    // ---- fc2a ----
    gemm_mma_kernel<<<dim3(4, GY), 256, SMEM>>>(A4, 128, Wt4, fc2a_b, 256,
                                                h4, 256, (__nv_bfloat16*)0, 0, 0, 0, 0, M);

    // ---- batchnorm stats ----
    bn_partial<<<512, BN_COLS>>>(h4, M, part);
    bn_finalize<<<1, BN_COLS>>>(part, 512, M, bn_g, bn_b, scale, shift);

    // ---- fc2b (fused BN apply + relu) ----
    fc2b_kernel<<<(M + 255) / 256, 256>>>(h4, fc2b_W, fc2b_b, scale, shift,
                                          out, M);
}

// round 12
// speedup vs baseline: 1.0334x; 1.0334x over previous
#include <cuda_runtime.h>
#include <cuda_bf16.h>
#include <cstdint>
#include <math.h>

// ---------------------------------------------------------------------------
// Problem constants
// ---------------------------------------------------------------------------
#define N_NODES 100000
#define M_PAD   100096          // 782 * 128
#define BN_COLS 256

// ---------------------------------------------------------------------------
// Scratch (device globals; zero-initialized; no allocation allowed)
// A_i layouts (bf16): [hi region (Kpad)][lo region (Kpad)], ld = 2*Kpad
//   A0: Kpad=256  (agg 0..99,  self 100..199, pad->255)
//   A1: Kpad=448  (agg 0..199, self 200..399, pad->447)
//   A2: Kpad=256  (agg 0..127, self 128..255)
//   A3: Kpad=128
//   A4: Kpad=128
// Wt_i (bf16): rows = padded N, cols = 2*Kpad: [W_hi | W_lo], zeros in pads
// ---------------------------------------------------------------------------
__device__ __align__(1024) __nv_bfloat16 g_A0[(size_t)M_PAD * 512];
__device__ __align__(1024) __nv_bfloat16 g_A1[(size_t)M_PAD * 896];
__device__ __align__(1024) __nv_bfloat16 g_A2[(size_t)M_PAD * 512];
__device__ __align__(1024) __nv_bfloat16 g_A3[(size_t)M_PAD * 256];
__device__ __align__(1024) __nv_bfloat16 g_A4[(size_t)M_PAD * 256];
__device__ float  g_h0[(size_t)M_PAD * 200];
__device__ float  g_h1[(size_t)M_PAD * 128];
__device__ float  g_h4[(size_t)M_PAD * 256];
__device__ __align__(1024) __nv_bfloat16 g_Wt0[256 * 512];
__device__ __align__(1024) __nv_bfloat16 g_Wt1[128 * 896];
__device__ __align__(1024) __nv_bfloat16 g_Wt2[128 * 512];
__device__ __align__(1024) __nv_bfloat16 g_Wt3[128 * 256];
__device__ __align__(1024) __nv_bfloat16 g_Wt4[256 * 256];
__device__ float  g_bias[3 * 256];
__device__ int    g_row_ptr[N_NODES + 1];
__device__ double g_part[512 * 512];
__device__ float  g_scale[BN_COLS];
__device__ float  g_shift[BN_COLS];

// ---------------------------------------------------------------------------
// PTX helpers (baseline features only; nothing sm_103a-gated)
// ---------------------------------------------------------------------------
__device__ __forceinline__ void cpa16(uint32_t dst, const void* src) {
    asm volatile("cp.async.cg.shared.global [%0], [%1], 16;\n"
                 :: "r"(dst), "l"(src));
}
__device__ __forceinline__ void cpa_commit() {
    asm volatile("cp.async.commit_group;\n" ::: "memory");
}
__device__ __forceinline__ void cpa_wait1() {
    asm volatile("cp.async.wait_group 1;\n" ::: "memory");
}
__device__ __forceinline__ void cpa_wait0() {
    asm volatile("cp.async.wait_group 0;\n" ::: "memory");
}
__device__ __forceinline__ void ldm_x4(uint32_t addr, uint32_t& r0, uint32_t& r1,
                                       uint32_t& r2, uint32_t& r3) {
    asm volatile("ldmatrix.sync.aligned.m8n8.x4.shared.b16 {%0,%1,%2,%3}, [%4];"
                 : "=r"(r0), "=r"(r1), "=r"(r2), "=r"(r3) : "r"(addr));
}
__device__ __forceinline__ void mma_bf16(float& c0, float& c1, float& c2, float& c3,
                                         uint32_t a0, uint32_t a1, uint32_t a2,
                                         uint32_t a3, uint32_t b0, uint32_t b1) {
    asm volatile(
        "mma.sync.aligned.m16n8k16.row.col.f32.bf16.bf16.f32 "
        "{%0,%1,%2,%3}, {%4,%5,%6,%7}, {%8,%9}, {%0,%1,%2,%3};"
        : "+f"(c0), "+f"(c1), "+f"(c2), "+f"(c3)
        : "r"(a0), "r"(a1), "r"(a2), "r"(a3), "r"(b0), "r"(b1));
}
__device__ __forceinline__ void split_bf16(float v, __nv_bfloat16& hi,
                                           __nv_bfloat16& lo) {
    hi = __float2bfloat16(v);
    lo = __float2bfloat16(v - __bfloat162float(hi));
}

// ---------------------------------------------------------------------------
// CSR row_ptr from sorted edge_row
// ---------------------------------------------------------------------------
__global__ void build_row_ptr(const int* __restrict__ row, int E, int N,
                              int* __restrict__ rp) {
    int i = blockIdx.x * blockDim.x + threadIdx.x;
    if (i > N) return;
    int lo = 0, hi = E;
    while (lo < hi) {
        int mid = (lo + hi) >> 1;
        if (row[mid] < i) lo = mid + 1; else hi = mid;
    }
    rp[i] = lo;
}

// ---------------------------------------------------------------------------
// Prep: x -> A0 self region (hi/lo bf16)
// ---------------------------------------------------------------------------
__global__ void xprep_kernel(const float* __restrict__ x,
                             __nv_bfloat16* __restrict__ A0) {
    int idx = blockIdx.x * blockDim.x + threadIdx.x;
    if (idx >= N_NODES * 100) return;
    int m = idx / 100, c = idx % 100;
    __nv_bfloat16 hi, lo;
    split_bf16(__ldg(x + idx), hi, lo);
    A0[(size_t)m * 512 + 100 + c] = hi;
    A0[(size_t)m * 512 + 356 + c] = lo;   // 256 + 100
}

// ---------------------------------------------------------------------------
// Prep: W (K x Nlog row-major; dual = [Wa; Wb]) -> Wt (N x 2*Kpad bf16)
// ---------------------------------------------------------------------------
__global__ void build_wt_kernel(const float* __restrict__ Wa,
                                const float* __restrict__ Wb,
                                int F, int Keff, int Kpad, int Nlog,
                                __nv_bfloat16* __restrict__ dst) {
    int idx = blockIdx.x * blockDim.x + threadIdx.x;
    if (idx >= Nlog * Keff) return;
    int n = idx / Keff, k = idx % Keff;
    float w = (k < F) ? __ldg(Wa + (size_t)k * Nlog + n)
                      : __ldg(Wb + (size_t)(k - F) * Nlog + n);
    __nv_bfloat16 hi, lo;
    split_bf16(w, hi, lo);
    dst[(size_t)n * (2 * Kpad) + k] = hi;
    dst[(size_t)n * (2 * Kpad) + Kpad + k] = lo;
}

__global__ void prep_bias_kernel(const float* b0, const float* bs0,
                                 const float* b1, const float* bs1,
                                 const float* b2, const float* bs2,
                                 float* __restrict__ bias) {
    int t = threadIdx.x;
    bias[t]       = (t < 200) ? b0[t] + bs0[t] : 0.f;
    bias[256 + t] = (t < 128) ? b1[t] + bs1[t] : 0.f;
    bias[512 + t] = (t < 128) ? b2[t] + bs2[t] : 0.f;
}

// ---------------------------------------------------------------------------
// SpMM: warp per node, NC float4 chunks per lane, 2-edge unroll.
// Edge loop is outermost: col/val read ONCE per edge; all NC gathers for an
// edge issued back-to-back (same row, +128B apart -> good ILP/locality).
// Deterministic accumulation order: edge i then i+1 per chunk.
// ---------------------------------------------------------------------------
template<int NC>
__global__ void __launch_bounds__(256) spmm_kernel(
    const float* __restrict__ src, int sstride,
    const int* __restrict__ col, const float* __restrict__ val,
    const int* __restrict__ rp,
    __nv_bfloat16* __restrict__ dstA, int ldA, int loOff, int F4) {
    int warp = (blockIdx.x * blockDim.x + threadIdx.x) >> 5;
    if (warp >= N_NODES) return;
    int lane = threadIdx.x & 31;
    int s = __ldg(rp + warp), e = __ldg(rp + warp + 1);
    __nv_bfloat16* arow = dstA + (size_t)warp * ldA;

    float4 acc[NC];
    bool act[NC];
#pragma unroll
    for (int j = 0; j < NC; ++j) {
        acc[j] = make_float4(0.f, 0.f, 0.f, 0.f);
        act[j] = (lane + j * 32) < F4;
    }

    int i = s;
    for (; i + 1 < e; i += 2) {
        int   c0 = __ldg(col + i),   c1 = __ldg(col + i + 1);
        float v0 = __ldg(val + i),   v1 = __ldg(val + i + 1);
        const float4* r0 = (const float4*)(src + (size_t)c0 * sstride);
        const float4* r1 = (const float4*)(src + (size_t)c1 * sstride);
#pragma unroll
        for (int j = 0; j < NC; ++j) {
            if (act[j]) {
                float4 x0 = __ldg(r0 + lane + j * 32);
                float4 x1 = __ldg(r1 + lane + j * 32);
                acc[j].x = fmaf(v0, x0.x, acc[j].x);
                acc[j].y = fmaf(v0, x0.y, acc[j].y);
                acc[j].z = fmaf(v0, x0.z, acc[j].z);
                acc[j].w = fmaf(v0, x0.w, acc[j].w);
                acc[j].x = fmaf(v1, x1.x, acc[j].x);
                acc[j].y = fmaf(v1, x1.y, acc[j].y);
                acc[j].z = fmaf(v1, x1.z, acc[j].z);
                acc[j].w = fmaf(v1, x1.w, acc[j].w);
            }
        }
    }
    if (i < e) {
        int   c0 = __ldg(col + i);
        float v0 = __ldg(val + i);
        const float4* r0 = (const float4*)(src + (size_t)c0 * sstride);
#pragma unroll
        for (int j = 0; j < NC; ++j) {
            if (act[j]) {
                float4 x0 = __ldg(r0 + lane + j * 32);
                acc[j].x = fmaf(v0, x0.x, acc[j].x);
                acc[j].y = fmaf(v0, x0.y, acc[j].y);
                acc[j].z = fmaf(v0, x0.z, acc[j].z);
                acc[j].w = fmaf(v0, x0.w, acc[j].w);
            }
        }
    }

#pragma unroll
    for (int j = 0; j < NC; ++j) {
        if (!act[j]) continue;
        int f = lane + j * 32;
        __nv_bfloat16 h0, l0, h1, l1, h2, l2, h3, l3;
        split_bf16(acc[j].x, h0, l0); split_bf16(acc[j].y, h1, l1);
        split_bf16(acc[j].z, h2, l2); split_bf16(acc[j].w, h3, l3);
        __nv_bfloat162* ph = (__nv_bfloat162*)(arow + f * 4);
        __nv_bfloat162* pl = (__nv_bfloat162*)(arow + loOff + f * 4);
        ph[0] = __nv_bfloat162(h0, h1); ph[1] = __nv_bfloat162(h2, h3);
        pl[0] = __nv_bfloat162(l0, l1); pl[1] = __nv_bfloat162(l2, l3);
    }
}

// ---------------------------------------------------------------------------
// bf16-split GEMM via mma.sync (HMMA path, baseline PTX).
// C(128 x 64 per CTA) = A @ Wt^T with 3-phase split:
//   (Ahi,Whi), (Alo,Whi), (Ahi,Wlo)   [phases = K regions, same accumulator]
// A: row-major, ld = 2*Kpad bf16. Wt: Nrows x 2*Kpad bf16 (B col-major view).
// K chunks of 64; 2-stage cp.async pipeline; padded smem stride 72 bf16.
// 8 warps: 4(M) x 2(N); warp tile 32x32 = 2 m16 x 4 n8 fragments.
// Epilogue: bias + relu; writes fp32 C (optional) and bf16 hi/lo next-A.
// ---------------------------------------------------------------------------
__global__ void __launch_bounds__(256) gemm_mma_kernel(
    const __nv_bfloat16* __restrict__ A, int Kpad,
    const __nv_bfloat16* __restrict__ Wt,
    const float* __restrict__ bias, int Nlog,
    float* __restrict__ Cf, int ldc,
    __nv_bfloat16* __restrict__ nxt, int ldn, int hiOff, int loOff,
    int relu, int M) {
    extern __shared__ __align__(16) char smem[];
    const int tid  = threadIdx.x;
    const int l    = tid & 31;
    const int wid  = tid >> 5;
    const int wm   = wid >> 1;        // 0..3
    const int wn   = wid & 1;         // 0..1
    const int row0 = blockIdx.y * 128;
    const int col0 = blockIdx.x * 64;
    const int ldA  = 2 * Kpad;
    const int R    = Kpad >> 6;
    const int C    = 3 * R;

    const uint32_t sbase = (uint32_t)__cvta_generic_to_shared(smem);
    const uint32_t aSt   = 128 * 72 * 2;   // 18432 B per A stage
    const uint32_t bSt   = 64 * 72 * 2;    //  9216 B per B stage
    const uint32_t stage = aSt + bSt;      // 27648

    float acc[2][4][4];
#pragma unroll
    for (int i = 0; i < 2; ++i)
#pragma unroll
        for (int j = 0; j < 4; ++j)
#pragma unroll
            for (int k = 0; k < 4; ++k) acc[i][j][k] = 0.f;

    auto load_chunk = [&](int c) {
        const int s = c & 1;
        const uint32_t aB = sbase + (uint32_t)s * stage;
        const uint32_t bB = aB + aSt;
        const int reg = c / R, wi = c - reg * R;
        const int aCol = (reg == 1 ? Kpad : 0) + wi * 64;
        const int wCol = (reg == 2 ? Kpad : 0) + wi * 64;
        const __nv_bfloat16* aSrc = A + (size_t)row0 * ldA + aCol;
#pragma unroll
        for (int it = 0; it < 4; ++it) {
            int idx = tid + it * 256;
            int r = idx >> 3, g = idx & 7;
            cpa16(aB + (uint32_t)(r * 72 + g * 8) * 2,
                  aSrc + (size_t)r * ldA + g * 8);
        }
        const __nv_bfloat16* wSrc = Wt + (size_t)col0 * ldA + wCol;
#pragma unroll
        for (int it = 0; it < 2; ++it) {
            int idx = tid + it * 256;
            int r = idx >> 3, g = idx & 7;
            cpa16(bB + (uint32_t)(r * 72 + g * 8) * 2,
                  wSrc + (size_t)r * ldA + g * 8);
        }
        cpa_commit();
    };

    load_chunk(0);
    if (C > 1) load_chunk(1);

    // ldmatrix per-lane base offsets (bytes)
    const uint32_t aLdm = (uint32_t)(((l & 15) * 72 + (l >> 4) * 8) * 2
                                     + (wm * 32) * 144);
    const uint32_t bLdm = (uint32_t)((((l & 7) + ((l >> 4) << 3)) * 72
                                     + ((l >> 3) & 1) * 8) * 2
                                     + (wn * 32) * 144);

    for (int c = 0; c < C; ++c) {
        if (c + 1 < C) cpa_wait1(); else cpa_wait0();
        __syncthreads();
        const int s = c & 1;
        const uint32_t aB = sbase + (uint32_t)s * stage;
        const uint32_t bB = aB + aSt;
#pragma unroll
        for (int ks = 0; ks < 4; ++ks) {
            uint32_t af[2][4], bf[2][4];
#pragma unroll
            for (int mt = 0; mt < 2; ++mt)
                ldm_x4(aB + aLdm + (uint32_t)(ks * 32 + mt * 16 * 144),
                       af[mt][0], af[mt][1], af[mt][2], af[mt][3]);
#pragma unroll
            for (int np = 0; np < 2; ++np)
                ldm_x4(bB + bLdm + (uint32_t)(ks * 32 + np * 16 * 144),
                       bf[np][0], bf[np][1], bf[np][2], bf[np][3]);
#pragma unroll
            for (int mt = 0; mt < 2; ++mt)
#pragma unroll
                for (int nt = 0; nt < 4; ++nt)
                    mma_bf16(acc[mt][nt][0], acc[mt][nt][1],
                             acc[mt][nt][2], acc[mt][nt][3],
                             af[mt][0], af[mt][1], af[mt][2], af[mt][3],
                             bf[nt >> 1][(nt & 1) * 2],
                             bf[nt >> 1][(nt & 1) * 2 + 1]);
        }
        __syncthreads();
        if (c + 2 < C) load_chunk(c + 2);
    }

    // ---- epilogue ----
    const int mrow = l >> 2;          // 0..7
    const int ncol = (l & 3) * 2;
#pragma unroll
    for (int mt = 0; mt < 2; ++mt) {
        const int rbase = row0 + wm * 32 + mt * 16 + mrow;
#pragma unroll
        for (int h = 0; h < 2; ++h) {
            const int row = rbase + h * 8;
            if (row >= M) continue;
            float* crow = Cf ? Cf + (size_t)row * ldc : (float*)0;
            __nv_bfloat16* nrow = nxt ? nxt + (size_t)row * ldn
                                      : (__nv_bfloat16*)0;
#pragma unroll
            for (int nt = 0; nt < 4; ++nt) {
                const int cg = col0 + wn * 32 + nt * 8 + ncol;
                if (cg >= Nlog) continue;
                float v0 = acc[mt][nt][h * 2 + 0] + __ldg(bias + cg);
                float v1 = acc[mt][nt][h * 2 + 1] + __ldg(bias + cg + 1);
                if (relu) { v0 = fmaxf(v0, 0.f); v1 = fmaxf(v1, 0.f); }
                if (crow) {
                    float2 fv; fv.x = v0; fv.y = v1;
                    *(float2*)(crow + cg) = fv;
                }
                if (nrow) {
                    __nv_bfloat16 h0, l0, h1, l1;
                    split_bf16(v0, h0, l0);
                    split_bf16(v1, h1, l1);
                    *(__nv_bfloat162*)(nrow + hiOff + cg) = __nv_bfloat162(h0, h1);
                    *(__nv_bfloat162*)(nrow + loOff + cg) = __nv_bfloat162(l0, l1);
                }
            }
        }
    }
}

// ---------------------------------------------------------------------------
// fc2b (fused BN apply + relu): out = relu(h4*scale+shift) @ W + b
// ---------------------------------------------------------------------------
__global__ void __launch_bounds__(256) fc2b_kernel(
    const float* __restrict__ A, const float* __restrict__ W,
    const float* __restrict__ bias,
    const float* __restrict__ scale, const float* __restrict__ shift,
    float* __restrict__ out, int M) {
    __shared__ float Ws[256][20];
    __shared__ float sS[256], sB[256];
    for (int i = threadIdx.x; i < 256 * 18; i += 256)
        Ws[i / 18][i % 18] = __ldg(W + i);
    Ws[threadIdx.x][18] = 0.f;
    Ws[threadIdx.x][19] = 0.f;
    sS[threadIdx.x] = __ldg(scale + threadIdx.x);
    sB[threadIdx.x] = __ldg(shift + threadIdx.x);
    __syncthreads();

    int row = blockIdx.x * 256 + threadIdx.x;
    if (row >= M) return;
    const float4* a = (const float4*)(A + (size_t)row * 256);

    float acc[18];
#pragma unroll
    for (int j = 0; j < 18; ++j) acc[j] = 0.f;

    for (int k4 = 0; k4 < 64; ++k4) {
        float4 av = __ldg(a + k4);
        const int kb = k4 * 4;
        float avs[4];
        avs[0] = fmaxf(fmaf(av.x, sS[kb + 0], sB[kb + 0]), 0.f);
        avs[1] = fmaxf(fmaf(av.y, sS[kb + 1], sB[kb + 1]), 0.f);
        avs[2] = fmaxf(fmaf(av.z, sS[kb + 2], sB[kb + 2]), 0.f);
        avs[3] = fmaxf(fmaf(av.w, sS[kb + 3], sB[kb + 3]), 0.f);
#pragma unroll
        for (int u = 0; u < 4; ++u) {
            int k = kb + u;
            float va = avs[u];
            const float* wr = &Ws[k][0];
            float4 w0 = *(const float4*)(wr + 0);
            float4 w1 = *(const float4*)(wr + 4);
            float4 w2 = *(const float4*)(wr + 8);
            float4 w3 = *(const float4*)(wr + 12);
            float2 w4 = *(const float2*)(wr + 16);
            acc[0]  = fmaf(va, w0.x, acc[0]);  acc[1]  = fmaf(va, w0.y, acc[1]);
            acc[2]  = fmaf(va, w0.z, acc[2]);  acc[3]  = fmaf(va, w0.w, acc[3]);
            acc[4]  = fmaf(va, w1.x, acc[4]);  acc[5]  = fmaf(va, w1.y, acc[5]);
            acc[6]  = fmaf(va, w1.z, acc[6]);  acc[7]  = fmaf(va, w1.w, acc[7]);
            acc[8]  = fmaf(va, w2.x, acc[8]);  acc[9]  = fmaf(va, w2.y, acc[9]);
            acc[10] = fmaf(va, w2.z, acc[10]); acc[11] = fmaf(va, w2.w, acc[11]);
            acc[12] = fmaf(va, w3.x, acc[12]); acc[13] = fmaf(va, w3.y, acc[13]);
            acc[14] = fmaf(va, w3.z, acc[14]); acc[15] = fmaf(va, w3.w, acc[15]);
            acc[16] = fmaf(va, w4.x, acc[16]); acc[17] = fmaf(va, w4.y, acc[17]);
        }
    }
    float* orow = out + (size_t)row * 18;
#pragma unroll
    for (int j = 0; j < 18; ++j) orow[j] = acc[j] + __ldg(bias + j);
}

// ---------------------------------------------------------------------------
// Batchnorm: deterministic two-stage reduction in fp64
// ---------------------------------------------------------------------------
__global__ void __launch_bounds__(BN_COLS) bn_partial(
    const float* __restrict__ h, int M, double* __restrict__ part) {
    int c = threadIdx.x;
    double s = 0.0, q = 0.0;
    for (int r = blockIdx.x; r < M; r += gridDim.x) {
        double v = (double)h[(size_t)r * BN_COLS + c];
        s += v;
        q += v * v;
    }
    part[blockIdx.x * 512 + c]       = s;
    part[blockIdx.x * 512 + 256 + c] = q;
}

__global__ void __launch_bounds__(BN_COLS) bn_finalize(
    const double* __restrict__ part, int G, int M,
    const float* __restrict__ gamma, const float* __restrict__ beta,
    float* __restrict__ scale, float* __restrict__ shift) {
    int c = threadIdx.x;
    double s = 0.0, q = 0.0;
    for (int i = 0; i < G; ++i) {
        s += part[i * 512 + c];
        q += part[i * 512 + 256 + c];
    }
    double mean = s / M;
    double var  = q / M - mean * mean;
    float sc = gamma[c] * rsqrtf((float)var + 1e-5f);
    scale[c] = sc;
    shift[c] = beta[c] - (float)mean * sc;
}

// ---------------------------------------------------------------------------
// Launcher (R10 ordering restored: xprep warms L2 with x before spmm0)
// ---------------------------------------------------------------------------
extern "C" void kernel_launch(void* const* d_in, const int* in_sizes, int n_in,
                              void* d_out, int out_size) {
    const float* x        = (const float*)d_in[0];
    const int*   edge_row = (const int*)  d_in[1];
    const int*   edge_col = (const int*)  d_in[2];
    const float* edge_val = (const float*)d_in[3];
    const float* gc0_W  = (const float*)d_in[4];
    const float* gc0_b  = (const float*)d_in[5];
    const float* gc0_Ws = (const float*)d_in[6];
    const float* gc0_bs = (const float*)d_in[7];
    const float* gc1_W  = (const float*)d_in[8];
    const float* gc1_b  = (const float*)d_in[9];
    const float* gc1_Ws = (const float*)d_in[10];
    const float* gc1_bs = (const float*)d_in[11];
    const float* gc2_W  = (const float*)d_in[12];
    const float* gc2_b  = (const float*)d_in[13];
    const float* gc2_Ws = (const float*)d_in[14];
    const float* gc2_bs = (const float*)d_in[15];
    const float* fc1_W  = (const float*)d_in[16];
    const float* fc1_b  = (const float*)d_in[17];
    const float* fc2a_W = (const float*)d_in[18];
    const float* fc2a_b = (const float*)d_in[19];
    const float* bn_g   = (const float*)d_in[20];
    const float* bn_b   = (const float*)d_in[21];
    const float* fc2b_W = (const float*)d_in[22];
    const float* fc2b_b = (const float*)d_in[23];
    float* out = (float*)d_out;

    const int M = N_NODES;
    const int E = in_sizes[1];

    __nv_bfloat16 *A0, *A1, *A2, *A3, *A4, *Wt0, *Wt1, *Wt2, *Wt3, *Wt4;
    float *h0, *h1, *h4, *bias, *scale, *shift;
    int* rp;
    double* part;
    cudaGetSymbolAddress((void**)&A0,  g_A0);
    cudaGetSymbolAddress((void**)&A1,  g_A1);
    cudaGetSymbolAddress((void**)&A2,  g_A2);
    cudaGetSymbolAddress((void**)&A3,  g_A3);
    cudaGetSymbolAddress((void**)&A4,  g_A4);
    cudaGetSymbolAddress((void**)&Wt0, g_Wt0);
    cudaGetSymbolAddress((void**)&Wt1, g_Wt1);
    cudaGetSymbolAddress((void**)&Wt2, g_Wt2);
    cudaGetSymbolAddress((void**)&Wt3, g_Wt3);
    cudaGetSymbolAddress((void**)&Wt4, g_Wt4);
    cudaGetSymbolAddress((void**)&h0,  g_h0);
    cudaGetSymbolAddress((void**)&h1,  g_h1);
    cudaGetSymbolAddress((void**)&h4,  g_h4);
    cudaGetSymbolAddress((void**)&bias, g_bias);
    cudaGetSymbolAddress((void**)&rp,   g_row_ptr);
    cudaGetSymbolAddress((void**)&part, g_part);
    cudaGetSymbolAddress((void**)&scale, g_scale);
    cudaGetSymbolAddress((void**)&shift, g_shift);

    // dynamic smem: 2 stages * (18432 + 9216) = 55296 B
    const int SMEM = 55296;
    cudaFuncSetAttribute(gemm_mma_kernel,
                         cudaFuncAttributeMaxDynamicSharedMemorySize, SMEM);

    // ---- prep ----
    build_row_ptr<<<(M + 256) / 256, 256>>>(edge_row, E, M, rp);
    xprep_kernel<<<(M * 100 + 255) / 256, 256>>>(x, A0);
    build_wt_kernel<<<(200 * 200 + 255) / 256, 256>>>(gc0_W, gc0_Ws, 100, 200, 256, 200, Wt0);
    build_wt_kernel<<<(128 * 400 + 255) / 256, 256>>>(gc1_W, gc1_Ws, 200, 400, 448, 128, Wt1);
    build_wt_kernel<<<(128 * 256 + 255) / 256, 256>>>(gc2_W, gc2_Ws, 128, 256, 256, 128, Wt2);
    build_wt_kernel<<<(128 * 128 + 255) / 256, 256>>>(fc1_W, fc1_W, 128, 128, 128, 128, Wt3);
    build_wt_kernel<<<(256 * 128 + 255) / 256, 256>>>(fc2a_W, fc2a_W, 128, 128, 128, 256, Wt4);
    prep_bias_kernel<<<1, 256>>>(gc0_b, gc0_bs, gc1_b, gc1_bs, gc2_b, gc2_bs, bias);

    const int spmm_grid = (M + 7) / 8;    // 8 warps / 256-thread block
    const int GY = 782;                   // M tiles of 128

    // ---- layer 0: agg(x)->A0[:,0:100]; h0 = relu([agg|x]@W0+b) ----
    spmm_kernel<1><<<spmm_grid, 256>>>(x, 100, edge_col, edge_val, rp,
                                       A0, 512, 256, 25);
    gemm_mma_kernel<<<dim3(4, GY), 256, SMEM>>>(A0, 256, Wt0, bias, 200,
                                                h0, 200, A1, 896, 200, 648, 1, M);
    // ---- layer 1 (F4=50 -> 2 chunks per lane) ----
    spmm_kernel<2><<<spmm_grid, 256>>>(h0, 200, edge_col, edge_val, rp,
                                       A1, 896, 448, 50);
    gemm_mma_kernel<<<dim3(2, GY), 256, SMEM>>>(A1, 448, Wt1, bias + 256, 128,
                                                h1, 128, A2, 512, 128, 384, 1, M);
    // ---- layer 2 ----
    spmm_kernel<1><<<spmm_grid, 256>>>(h1, 128, edge_col, edge_val, rp,
                                       A2, 512, 256, 32);
    gemm_mma_kernel<<<dim3(2, GY), 256, SMEM>>>(A2, 256, Wt2, bias + 512, 128,
                                                (float*)0, 0, A3, 256, 0, 128, 1, M);
    // ---- fc1 ----
    gemm_mma_kernel<<<dim3(2, GY), 256, SMEM>>>(A3, 128, Wt3, fc1_b, 128,
                                                (float*)0, 0, A4, 256, 0, 128, 1, M);
    // ---- fc2a ----
    gemm_mma_kernel<<<dim3(4, GY), 256, SMEM>>>(A4, 128, Wt4, fc2a_b, 256,
                                                h4, 256, (__nv_bfloat16*)0, 0, 0, 0, 0, M);

    // ---- batchnorm stats ----
    bn_partial<<<512, BN_COLS>>>(h4, M, part);
    bn_finalize<<<1, BN_COLS>>>(part, 512, M, bn_g, bn_b, scale, shift);

    // ---- fc2b (fused BN apply + relu) ----
    fc2b_kernel<<<(M + 255) / 256, 256>>>(h4, fc2b_W, fc2b_b, scale, shift,
                                          out, M);
}

// round 13
// speedup vs baseline: 1.0873x; 1.0522x over previous
#include <cuda_runtime.h>
#include <cuda_bf16.h>
#include <cstdint>
#include <math.h>

// ---------------------------------------------------------------------------
// Problem constants
// ---------------------------------------------------------------------------
#define N_NODES 100000
#define M_PAD   100096          // 782 * 128
#define BN_COLS 256

// ---------------------------------------------------------------------------
// Scratch (device globals; zero-initialized; no allocation allowed)
// A_i layouts (bf16): [hi region (Kpad)][lo region (Kpad)], ld = 2*Kpad
//   A0: Kpad=256  (agg 0..99,  self 100..199, pad->255)
//   A1: Kpad=448  (agg 0..199, self 200..399, pad->447)
//   A2: Kpad=256  (agg 0..127, self 128..255)
//   A3: Kpad=128
//   A4: Kpad=128
// Wt_i (bf16): rows = padded N, cols = 2*Kpad: [W_hi | W_lo], zeros in pads
// ---------------------------------------------------------------------------
__device__ __align__(1024) __nv_bfloat16 g_A0[(size_t)M_PAD * 512];
__device__ __align__(1024) __nv_bfloat16 g_A1[(size_t)M_PAD * 896];
__device__ __align__(1024) __nv_bfloat16 g_A2[(size_t)M_PAD * 512];
__device__ __align__(1024) __nv_bfloat16 g_A3[(size_t)M_PAD * 256];
__device__ __align__(1024) __nv_bfloat16 g_A4[(size_t)M_PAD * 256];
__device__ float  g_h0[(size_t)M_PAD * 200];
__device__ float  g_h1[(size_t)M_PAD * 128];
__device__ float  g_h4[(size_t)M_PAD * 256];
__device__ __align__(1024) __nv_bfloat16 g_Wt0[256 * 512];
__device__ __align__(1024) __nv_bfloat16 g_Wt1[128 * 896];
__device__ __align__(1024) __nv_bfloat16 g_Wt2[128 * 512];
__device__ __align__(1024) __nv_bfloat16 g_Wt3[128 * 256];
__device__ __align__(1024) __nv_bfloat16 g_Wt4[256 * 256];
__device__ float  g_bias[3 * 256];
__device__ int    g_row_ptr[N_NODES + 1];
__device__ double g_part[512 * 512];
__device__ float  g_scale[BN_COLS];
__device__ float  g_shift[BN_COLS];

// ---------------------------------------------------------------------------
// PTX helpers (baseline features only; nothing sm_103a-gated)
// ---------------------------------------------------------------------------
__device__ __forceinline__ void cpa16(uint32_t dst, const void* src) {
    asm volatile("cp.async.cg.shared.global [%0], [%1], 16;\n"
                 :: "r"(dst), "l"(src));
}
__device__ __forceinline__ void cpa_commit() {
    asm volatile("cp.async.commit_group;\n" ::: "memory");
}
__device__ __forceinline__ void cpa_wait1() {
    asm volatile("cp.async.wait_group 1;\n" ::: "memory");
}
__device__ __forceinline__ void cpa_wait0() {
    asm volatile("cp.async.wait_group 0;\n" ::: "memory");
}
__device__ __forceinline__ void ldm_x4(uint32_t addr, uint32_t& r0, uint32_t& r1,
                                       uint32_t& r2, uint32_t& r3) {
    asm volatile("ldmatrix.sync.aligned.m8n8.x4.shared.b16 {%0,%1,%2,%3}, [%4];"
                 : "=r"(r0), "=r"(r1), "=r"(r2), "=r"(r3) : "r"(addr));
}
__device__ __forceinline__ void mma_bf16(float& c0, float& c1, float& c2, float& c3,
                                         uint32_t a0, uint32_t a1, uint32_t a2,
                                         uint32_t a3, uint32_t b0, uint32_t b1) {
    asm volatile(
        "mma.sync.aligned.m16n8k16.row.col.f32.bf16.bf16.f32 "
        "{%0,%1,%2,%3}, {%4,%5,%6,%7}, {%8,%9}, {%0,%1,%2,%3};"
        : "+f"(c0), "+f"(c1), "+f"(c2), "+f"(c3)
        : "r"(a0), "r"(a1), "r"(a2), "r"(a3), "r"(b0), "r"(b1));
}
__device__ __forceinline__ void split_bf16(float v, __nv_bfloat16& hi,
                                           __nv_bfloat16& lo) {
    hi = __float2bfloat16(v);
    lo = __float2bfloat16(v - __bfloat162float(hi));
}

// ---------------------------------------------------------------------------
// CSR row_ptr from sorted edge_row
// ---------------------------------------------------------------------------
__global__ void build_row_ptr(const int* __restrict__ row, int E, int N,
                              int* __restrict__ rp) {
    int i = blockIdx.x * blockDim.x + threadIdx.x;
    if (i > N) return;
    int lo = 0, hi = E;
    while (lo < hi) {
        int mid = (lo + hi) >> 1;
        if (row[mid] < i) lo = mid + 1; else hi = mid;
    }
    rp[i] = lo;
}

// ---------------------------------------------------------------------------
// Prep: x -> A0 self region (hi/lo bf16)
// ---------------------------------------------------------------------------
__global__ void xprep_kernel(const float* __restrict__ x,
                             __nv_bfloat16* __restrict__ A0) {
    int idx = blockIdx.x * blockDim.x + threadIdx.x;
    if (idx >= N_NODES * 100) return;
    int m = idx / 100, c = idx % 100;
    __nv_bfloat16 hi, lo;
    split_bf16(__ldg(x + idx), hi, lo);
    A0[(size_t)m * 512 + 100 + c] = hi;
    A0[(size_t)m * 512 + 356 + c] = lo;   // 256 + 100
}

// ---------------------------------------------------------------------------
// Prep: W (K x Nlog row-major; dual = [Wa; Wb]) -> Wt (N x 2*Kpad bf16)
// ---------------------------------------------------------------------------
__global__ void build_wt_kernel(const float* __restrict__ Wa,
                                const float* __restrict__ Wb,
                                int F, int Keff, int Kpad, int Nlog,
                                __nv_bfloat16* __restrict__ dst) {
    int idx = blockIdx.x * blockDim.x + threadIdx.x;
    if (idx >= Nlog * Keff) return;
    int n = idx / Keff, k = idx % Keff;
    float w = (k < F) ? __ldg(Wa + (size_t)k * Nlog + n)
                      : __ldg(Wb + (size_t)(k - F) * Nlog + n);
    __nv_bfloat16 hi, lo;
    split_bf16(w, hi, lo);
    dst[(size_t)n * (2 * Kpad) + k] = hi;
    dst[(size_t)n * (2 * Kpad) + Kpad + k] = lo;
}

__global__ void prep_bias_kernel(const float* b0, const float* bs0,
                                 const float* b1, const float* bs1,
                                 const float* b2, const float* bs2,
                                 float* __restrict__ bias) {
    int t = threadIdx.x;
    bias[t]       = (t < 200) ? b0[t] + bs0[t] : 0.f;
    bias[256 + t] = (t < 128) ? b1[t] + bs1[t] : 0.f;
    bias[512 + t] = (t < 128) ? b2[t] + bs2[t] : 0.f;
}

// ---------------------------------------------------------------------------
// SpMM: warp per node, NC float4 chunks per lane, 2-edge unroll.
// ---------------------------------------------------------------------------
template<int NC>
__global__ void __launch_bounds__(256) spmm_kernel(
    const float* __restrict__ src, int sstride,
    const int* __restrict__ col, const float* __restrict__ val,
    const int* __restrict__ rp,
    __nv_bfloat16* __restrict__ dstA, int ldA, int loOff, int F4) {
    int warp = (blockIdx.x * blockDim.x + threadIdx.x) >> 5;
    if (warp >= N_NODES) return;
    int lane = threadIdx.x & 31;
    int s = __ldg(rp + warp), e = __ldg(rp + warp + 1);
    __nv_bfloat16* arow = dstA + (size_t)warp * ldA;

    float4 acc[NC];
    bool act[NC];
#pragma unroll
    for (int j = 0; j < NC; ++j) {
        acc[j] = make_float4(0.f, 0.f, 0.f, 0.f);
        act[j] = (lane + j * 32) < F4;
    }

    int i = s;
    for (; i + 1 < e; i += 2) {
        int   c0 = __ldg(col + i),   c1 = __ldg(col + i + 1);
        float v0 = __ldg(val + i),   v1 = __ldg(val + i + 1);
        const float4* r0 = (const float4*)(src + (size_t)c0 * sstride);
        const float4* r1 = (const float4*)(src + (size_t)c1 * sstride);
#pragma unroll
        for (int j = 0; j < NC; ++j) {
            if (act[j]) {
                float4 x0 = __ldg(r0 + lane + j * 32);
                float4 x1 = __ldg(r1 + lane + j * 32);
                acc[j].x = fmaf(v0, x0.x, acc[j].x);
                acc[j].y = fmaf(v0, x0.y, acc[j].y);
                acc[j].z = fmaf(v0, x0.z, acc[j].z);
                acc[j].w = fmaf(v0, x0.w, acc[j].w);
                acc[j].x = fmaf(v1, x1.x, acc[j].x);
                acc[j].y = fmaf(v1, x1.y, acc[j].y);
                acc[j].z = fmaf(v1, x1.z, acc[j].z);
                acc[j].w = fmaf(v1, x1.w, acc[j].w);
            }
        }
    }
    if (i < e) {
        int   c0 = __ldg(col + i);
        float v0 = __ldg(val + i);
        const float4* r0 = (const float4*)(src + (size_t)c0 * sstride);
#pragma unroll
        for (int j = 0; j < NC; ++j) {
            if (act[j]) {
                float4 x0 = __ldg(r0 + lane + j * 32);
                acc[j].x = fmaf(v0, x0.x, acc[j].x);
                acc[j].y = fmaf(v0, x0.y, acc[j].y);
                acc[j].z = fmaf(v0, x0.z, acc[j].z);
                acc[j].w = fmaf(v0, x0.w, acc[j].w);
            }
        }
    }

#pragma unroll
    for (int j = 0; j < NC; ++j) {
        if (!act[j]) continue;
        int f = lane + j * 32;
        __nv_bfloat16 h0, l0, h1, l1, h2, l2, h3, l3;
        split_bf16(acc[j].x, h0, l0); split_bf16(acc[j].y, h1, l1);
        split_bf16(acc[j].z, h2, l2); split_bf16(acc[j].w, h3, l3);
        __nv_bfloat162* ph = (__nv_bfloat162*)(arow + f * 4);
        __nv_bfloat162* pl = (__nv_bfloat162*)(arow + loOff + f * 4);
        ph[0] = __nv_bfloat162(h0, h1); ph[1] = __nv_bfloat162(h2, h3);
        pl[0] = __nv_bfloat162(l0, l1); pl[1] = __nv_bfloat162(l2, l3);
    }
}

// ---------------------------------------------------------------------------
// bf16-split GEMM via mma.sync — operand-reuse mainloop.
// Per K-chunk of 64, ALL FOUR tiles (Ahi, Alo, Whi, Wlo) are staged, and the
// three split passes  acc += Ahi*Whi + Alo*Whi + Ahi*Wlo  run from registers.
// vs the 3-region version this cuts smem loads from 3R A + 3R W tiles to
// 2R + 2R (33% less L2 traffic), same MMA and ldmatrix count.
// smem/stage = 2*18432 (A) + 2*9216 (W) = 55296 B; 2 stages = 110592 B.
// 8 warps: 4(M) x 2(N); warp tile 32x32; __launch_bounds__(256,2).
// ---------------------------------------------------------------------------
__global__ void __launch_bounds__(256, 2) gemm_mma_kernel(
    const __nv_bfloat16* __restrict__ A, int Kpad,
    const __nv_bfloat16* __restrict__ Wt,
    const float* __restrict__ bias, int Nlog,
    float* __restrict__ Cf, int ldc,
    __nv_bfloat16* __restrict__ nxt, int ldn, int hiOff, int loOff,
    int relu, int M) {
    extern __shared__ __align__(16) char smem[];
    const int tid  = threadIdx.x;
    const int l    = tid & 31;
    const int wid  = tid >> 5;
    const int wm   = wid >> 1;        // 0..3
    const int wn   = wid & 1;         // 0..1
    const int row0 = blockIdx.y * 128;
    const int col0 = blockIdx.x * 64;
    const int ldA  = 2 * Kpad;
    const int R    = Kpad >> 6;       // K-chunks (each covers hi+lo+both W)

    const uint32_t sbase = (uint32_t)__cvta_generic_to_shared(smem);
    const uint32_t AHI = 0, ALO = 18432, WHI = 36864, WLO = 46080;
    const uint32_t stage = 55296;

    float acc[2][4][4];
#pragma unroll
    for (int i = 0; i < 2; ++i)
#pragma unroll
        for (int j = 0; j < 4; ++j)
#pragma unroll
            for (int k = 0; k < 4; ++k) acc[i][j][k] = 0.f;

    auto load_chunk = [&](int c) {
        const uint32_t sb = sbase + (uint32_t)(c & 1) * stage;
        const int kc = c * 64;
        const __nv_bfloat16* aHi = A + (size_t)row0 * ldA + kc;
        const __nv_bfloat16* aLo = aHi + Kpad;
#pragma unroll
        for (int it = 0; it < 4; ++it) {
            int idx = tid + it * 256;
            int r = idx >> 3, g = idx & 7;
            uint32_t so = (uint32_t)(r * 72 + g * 8) * 2;
            size_t  go = (size_t)r * ldA + g * 8;
            cpa16(sb + AHI + so, aHi + go);
            cpa16(sb + ALO + so, aLo + go);
        }
        const __nv_bfloat16* wHi = Wt + (size_t)col0 * ldA + kc;
        const __nv_bfloat16* wLo = wHi + Kpad;
#pragma unroll
        for (int it = 0; it < 2; ++it) {
            int idx = tid + it * 256;
            int r = idx >> 3, g = idx & 7;
            uint32_t so = (uint32_t)(r * 72 + g * 8) * 2;
            size_t  go = (size_t)r * ldA + g * 8;
            cpa16(sb + WHI + so, wHi + go);
            cpa16(sb + WLO + so, wLo + go);
        }
        cpa_commit();
    };

    load_chunk(0);
    if (R > 1) load_chunk(1);

    // ldmatrix per-lane base offsets (bytes) within each tile
    const uint32_t aLdm = (uint32_t)(((l & 15) * 72 + (l >> 4) * 8) * 2
                                     + (wm * 32) * 144);
    const uint32_t bLdm = (uint32_t)((((l & 7) + ((l >> 4) << 3)) * 72
                                     + ((l >> 3) & 1) * 8) * 2
                                     + (wn * 32) * 144);

    for (int c = 0; c < R; ++c) {
        if (c + 1 < R) cpa_wait1(); else cpa_wait0();
        __syncthreads();
        const uint32_t sb = sbase + (uint32_t)(c & 1) * stage;
#pragma unroll
        for (int ks = 0; ks < 4; ++ks) {
            const uint32_t ko = (uint32_t)(ks * 32);
            uint32_t af[2][4], al[2][4], bh[2][4], bl[2][4];
#pragma unroll
            for (int mt = 0; mt < 2; ++mt)
                ldm_x4(sb + AHI + aLdm + ko + (uint32_t)(mt * 16 * 144),
                       af[mt][0], af[mt][1], af[mt][2], af[mt][3]);
#pragma unroll
            for (int np = 0; np < 2; ++np)
                ldm_x4(sb + WHI + bLdm + ko + (uint32_t)(np * 16 * 144),
                       bh[np][0], bh[np][1], bh[np][2], bh[np][3]);
            // pass 1: Ahi * Whi
#pragma unroll
            for (int mt = 0; mt < 2; ++mt)
#pragma unroll
                for (int nt = 0; nt < 4; ++nt)
                    mma_bf16(acc[mt][nt][0], acc[mt][nt][1],
                             acc[mt][nt][2], acc[mt][nt][3],
                             af[mt][0], af[mt][1], af[mt][2], af[mt][3],
                             bh[nt >> 1][(nt & 1) * 2],
                             bh[nt >> 1][(nt & 1) * 2 + 1]);
#pragma unroll
            for (int mt = 0; mt < 2; ++mt)
                ldm_x4(sb + ALO + aLdm + ko + (uint32_t)(mt * 16 * 144),
                       al[mt][0], al[mt][1], al[mt][2], al[mt][3]);
            // pass 2: Alo * Whi
#pragma unroll
            for (int mt = 0; mt < 2; ++mt)
#pragma unroll
                for (int nt = 0; nt < 4; ++nt)
                    mma_bf16(acc[mt][nt][0], acc[mt][nt][1],
                             acc[mt][nt][2], acc[mt][nt][3],
                             al[mt][0], al[mt][1], al[mt][2], al[mt][3],
                             bh[nt >> 1][(nt & 1) * 2],
                             bh[nt >> 1][(nt & 1) * 2 + 1]);
#pragma unroll
            for (int np = 0; np < 2; ++np)
                ldm_x4(sb + WLO + bLdm + ko + (uint32_t)(np * 16 * 144),
                       bl[np][0], bl[np][1], bl[np][2], bl[np][3]);
            // pass 3: Ahi * Wlo
#pragma unroll
            for (int mt = 0; mt < 2; ++mt)
#pragma unroll
                for (int nt = 0; nt < 4; ++nt)
                    mma_bf16(acc[mt][nt][0], acc[mt][nt][1],
                             acc[mt][nt][2], acc[mt][nt][3],
                             af[mt][0], af[mt][1], af[mt][2], af[mt][3],
                             bl[nt >> 1][(nt & 1) * 2],
                             bl[nt >> 1][(nt & 1) * 2 + 1]);
        }
        __syncthreads();
        if (c + 2 < R) load_chunk(c + 2);
    }

    // ---- epilogue ----
    const int mrow = l >> 2;          // 0..7
    const int ncol = (l & 3) * 2;
#pragma unroll
    for (int mt = 0; mt < 2; ++mt) {
        const int rbase = row0 + wm * 32 + mt * 16 + mrow;
#pragma unroll
        for (int h = 0; h < 2; ++h) {
            const int row = rbase + h * 8;
            if (row >= M) continue;
            float* crow = Cf ? Cf + (size_t)row * ldc : (float*)0;
            __nv_bfloat16* nrow = nxt ? nxt + (size_t)row * ldn
                                      : (__nv_bfloat16*)0;
#pragma unroll
            for (int nt = 0; nt < 4; ++nt) {
                const int cg = col0 + wn * 32 + nt * 8 + ncol;
                if (cg >= Nlog) continue;
                float v0 = acc[mt][nt][h * 2 + 0] + __ldg(bias + cg);
                float v1 = acc[mt][nt][h * 2 + 1] + __ldg(bias + cg + 1);
                if (relu) { v0 = fmaxf(v0, 0.f); v1 = fmaxf(v1, 0.f); }
                if (crow) {
                    float2 fv; fv.x = v0; fv.y = v1;
                    *(float2*)(crow + cg) = fv;
                }
                if (nrow) {
                    __nv_bfloat16 h0, l0, h1, l1;
                    split_bf16(v0, h0, l0);
                    split_bf16(v1, h1, l1);
                    *(__nv_bfloat162*)(nrow + hiOff + cg) = __nv_bfloat162(h0, h1);
                    *(__nv_bfloat162*)(nrow + loOff + cg) = __nv_bfloat162(l0, l1);
                }
            }
        }
    }
}

// ---------------------------------------------------------------------------
// fc2b (fused BN apply + relu): out = relu(h4*scale+shift) @ W + b
// ---------------------------------------------------------------------------
__global__ void __launch_bounds__(256) fc2b_kernel(
    const float* __restrict__ A, const float* __restrict__ W,
    const float* __restrict__ bias,
    const float* __restrict__ scale, const float* __restrict__ shift,
    float* __restrict__ out, int M) {
    __shared__ float Ws[256][20];
    __shared__ float sS[256], sB[256];
    for (int i = threadIdx.x; i < 256 * 18; i += 256)
        Ws[i / 18][i % 18] = __ldg(W + i);
    Ws[threadIdx.x][18] = 0.f;
    Ws[threadIdx.x][19] = 0.f;
    sS[threadIdx.x] = __ldg(scale + threadIdx.x);
    sB[threadIdx.x] = __ldg(shift + threadIdx.x);
    __syncthreads();

    int row = blockIdx.x * 256 + threadIdx.x;
    if (row >= M) return;
    const float4* a = (const float4*)(A + (size_t)row * 256);

    float acc[18];
#pragma unroll
    for (int j = 0; j < 18; ++j) acc[j] = 0.f;

    for (int k4 = 0; k4 < 64; ++k4) {
        float4 av = __ldg(a + k4);
        const int kb = k4 * 4;
        float avs[4];
        avs[0] = fmaxf(fmaf(av.x, sS[kb + 0], sB[kb + 0]), 0.f);
        avs[1] = fmaxf(fmaf(av.y, sS[kb + 1], sB[kb + 1]), 0.f);
        avs[2] = fmaxf(fmaf(av.z, sS[kb + 2], sB[kb + 2]), 0.f);
        avs[3] = fmaxf(fmaf(av.w, sS[kb + 3], sB[kb + 3]), 0.f);
#pragma unroll
        for (int u = 0; u < 4; ++u) {
            int k = kb + u;
            float va = avs[u];
            const float* wr = &Ws[k][0];
            float4 w0 = *(const float4*)(wr + 0);
            float4 w1 = *(const float4*)(wr + 4);
            float4 w2 = *(const float4*)(wr + 8);
            float4 w3 = *(const float4*)(wr + 12);
            float2 w4 = *(const float2*)(wr + 16);
            acc[0]  = fmaf(va, w0.x, acc[0]);  acc[1]  = fmaf(va, w0.y, acc[1]);
            acc[2]  = fmaf(va, w0.z, acc[2]);  acc[3]  = fmaf(va, w0.w, acc[3]);
            acc[4]  = fmaf(va, w1.x, acc[4]);  acc[5]  = fmaf(va, w1.y, acc[5]);
            acc[6]  = fmaf(va, w1.z, acc[6]);  acc[7]  = fmaf(va, w1.w, acc[7]);
            acc[8]  = fmaf(va, w2.x, acc[8]);  acc[9]  = fmaf(va, w2.y, acc[9]);
            acc[10] = fmaf(va, w2.z, acc[10]); acc[11] = fmaf(va, w2.w, acc[11]);
            acc[12] = fmaf(va, w3.x, acc[12]); acc[13] = fmaf(va, w3.y, acc[13]);
            acc[14] = fmaf(va, w3.z, acc[14]); acc[15] = fmaf(va, w3.w, acc[15]);
            acc[16] = fmaf(va, w4.x, acc[16]); acc[17] = fmaf(va, w4.y, acc[17]);
        }
    }
    float* orow = out + (size_t)row * 18;
#pragma unroll
    for (int j = 0; j < 18; ++j) orow[j] = acc[j] + __ldg(bias + j);
}

// ---------------------------------------------------------------------------
// Batchnorm: deterministic two-stage reduction in fp64
// ---------------------------------------------------------------------------
__global__ void __launch_bounds__(BN_COLS) bn_partial(
    const float* __restrict__ h, int M, double* __restrict__ part) {
    int c = threadIdx.x;
    double s = 0.0, q = 0.0;
    for (int r = blockIdx.x; r < M; r += gridDim.x) {
        double v = (double)h[(size_t)r * BN_COLS + c];
        s += v;
        q += v * v;
    }
    part[blockIdx.x * 512 + c]       = s;
    part[blockIdx.x * 512 + 256 + c] = q;
}

__global__ void __launch_bounds__(BN_COLS) bn_finalize(
    const double* __restrict__ part, int G, int M,
    const float* __restrict__ gamma, const float* __restrict__ beta,
    float* __restrict__ scale, float* __restrict__ shift) {
    int c = threadIdx.x;
    double s = 0.0, q = 0.0;
    for (int i = 0; i < G; ++i) {
        s += part[i * 512 + c];
        q += part[i * 512 + 256 + c];
    }
    double mean = s / M;
    double var  = q / M - mean * mean;
    float sc = gamma[c] * rsqrtf((float)var + 1e-5f);
    scale[c] = sc;
    shift[c] = beta[c] - (float)mean * sc;
}

// ---------------------------------------------------------------------------
// Launcher
// ---------------------------------------------------------------------------
extern "C" void kernel_launch(void* const* d_in, const int* in_sizes, int n_in,
                              void* d_out, int out_size) {
    const float* x        = (const float*)d_in[0];
    const int*   edge_row = (const int*)  d_in[1];
    const int*   edge_col = (const int*)  d_in[2];
    const float* edge_val = (const float*)d_in[3];
    const float* gc0_W  = (const float*)d_in[4];
    const float* gc0_b  = (const float*)d_in[5];
    const float* gc0_Ws = (const float*)d_in[6];
    const float* gc0_bs = (const float*)d_in[7];
    const float* gc1_W  = (const float*)d_in[8];
    const float* gc1_b  = (const float*)d_in[9];
    const float* gc1_Ws = (const float*)d_in[10];
    const float* gc1_bs = (const float*)d_in[11];
    const float* gc2_W  = (const float*)d_in[12];
    const float* gc2_b  = (const float*)d_in[13];
    const float* gc2_Ws = (const float*)d_in[14];
    const float* gc2_bs = (const float*)d_in[15];
    const float* fc1_W  = (const float*)d_in[16];
    const float* fc1_b  = (const float*)d_in[17];
    const float* fc2a_W = (const float*)d_in[18];
    const float* fc2a_b = (const float*)d_in[19];
    const float* bn_g   = (const float*)d_in[20];
    const float* bn_b   = (const float*)d_in[21];
    const float* fc2b_W = (const float*)d_in[22];
    const float* fc2b_b = (const float*)d_in[23];
    float* out = (float*)d_out;

    const int M = N_NODES;
    const int E = in_sizes[1];

    __nv_bfloat16 *A0, *A1, *A2, *A3, *A4, *Wt0, *Wt1, *Wt2, *Wt3, *Wt4;
    float *h0, *h1, *h4, *bias, *scale, *shift;
    int* rp;
    double* part;
    cudaGetSymbolAddress((void**)&A0,  g_A0);
    cudaGetSymbolAddress((void**)&A1,  g_A1);
    cudaGetSymbolAddress((void**)&A2,  g_A2);
    cudaGetSymbolAddress((void**)&A3,  g_A3);
    cudaGetSymbolAddress((void**)&A4,  g_A4);
    cudaGetSymbolAddress((void**)&Wt0, g_Wt0);
    cudaGetSymbolAddress((void**)&Wt1, g_Wt1);
    cudaGetSymbolAddress((void**)&Wt2, g_Wt2);
    cudaGetSymbolAddress((void**)&Wt3, g_Wt3);
    cudaGetSymbolAddress((void**)&Wt4, g_Wt4);
    cudaGetSymbolAddress((void**)&h0,  g_h0);
    cudaGetSymbolAddress((void**)&h1,  g_h1);
    cudaGetSymbolAddress((void**)&h4,  g_h4);
    cudaGetSymbolAddress((void**)&bias, g_bias);
    cudaGetSymbolAddress((void**)&rp,   g_row_ptr);
    cudaGetSymbolAddress((void**)&part, g_part);
    cudaGetSymbolAddress((void**)&scale, g_scale);
    cudaGetSymbolAddress((void**)&shift, g_shift);

    // dynamic smem: 2 stages * 55296 = 110592 B
    const int SMEM = 110592;
    cudaFuncSetAttribute(gemm_mma_kernel,
                         cudaFuncAttributeMaxDynamicSharedMemorySize, SMEM);

    // ---- prep ----
    build_row_ptr<<<(M + 256) / 256, 256>>>(edge_row, E, M, rp);
    xprep_kernel<<<(M * 100 + 255) / 256, 256>>>(x, A0);
    build_wt_kernel<<<(200 * 200 + 255) / 256, 256>>>(gc0_W, gc0_Ws, 100, 200, 256, 200, Wt0);
    build_wt_kernel<<<(128 * 400 + 255) / 256, 256>>>(gc1_W, gc1_Ws, 200, 400, 448, 128, Wt1);
    build_wt_kernel<<<(128 * 256 + 255) / 256, 256>>>(gc2_W, gc2_Ws, 128, 256, 256, 128, Wt2);
    build_wt_kernel<<<(128 * 128 + 255) / 256, 256>>>(fc1_W, fc1_W, 128, 128, 128, 128, Wt3);
    build_wt_kernel<<<(256 * 128 + 255) / 256, 256>>>(fc2a_W, fc2a_W, 128, 128, 128, 256, Wt4);
    prep_bias_kernel<<<1, 256>>>(gc0_b, gc0_bs, gc1_b, gc1_bs, gc2_b, gc2_bs, bias);

    const int spmm_grid = (M + 7) / 8;    // 8 warps / 256-thread block
    const int GY = 782;                   // M tiles of 128

    // ---- layer 0: agg(x)->A0[:,0:100]; h0 = relu([agg|x]@W0+b) ----
    spmm_kernel<1><<<spmm_grid, 256>>>(x, 100, edge_col, edge_val, rp,
                                       A0, 512, 256, 25);
    gemm_mma_kernel<<<dim3(4, GY), 256, SMEM>>>(A0, 256, Wt0, bias, 200,
                                                h0, 200, A1, 896, 200, 648, 1, M);
    // ---- layer 1 (F4=50 -> 2 chunks per lane) ----
    spmm_kernel<2><<<spmm_grid, 256>>>(h0, 200, edge_col, edge_val, rp,
                                       A1, 896, 448, 50);
    gemm_mma_kernel<<<dim3(2, GY), 256, SMEM>>>(A1, 448, Wt1, bias + 256, 128,
                                                h1, 128, A2, 512, 128, 384, 1, M);
    // ---- layer 2 ----
    spmm_kernel<1><<<spmm_grid, 256>>>(h1, 128, edge_col, edge_val, rp,
                                       A2, 512, 256, 32);
    gemm_mma_kernel<<<dim3(2, GY), 256, SMEM>>>(A2, 256, Wt2, bias + 512, 128,
                                                (float*)0, 0, A3, 256, 0, 128, 1, M);
    // ---- fc1 ----
    gemm_mma_kernel<<<dim3(2, GY), 256, SMEM>>>(A3, 128, Wt3, fc1_b, 128,
                                                (float*)0, 0, A4, 256, 0, 128, 1, M);
    // ---- fc2a ----
    gemm_mma_kernel<<<dim3(4, GY), 256, SMEM>>>(A4, 128, Wt4, fc2a_b, 256,
                                                h4, 256, (__nv_bfloat16*)0, 0, 0, 0, 0, M);

    // ---- batchnorm stats ----
    bn_partial<<<512, BN_COLS>>>(h4, M, part);
    bn_finalize<<<1, BN_COLS>>>(part, 512, M, bn_g, bn_b, scale, shift);

    // ---- fc2b (fused BN apply + relu) ----
    fc2b_kernel<<<(M + 255) / 256, 256>>>(h4, fc2b_W, fc2b_b, scale, shift,
                                          out, M);
}